// round 1
// baseline (speedup 1.0000x reference)
#include <cuda_runtime.h>

// ---------------- sizes ----------------
constexpr int B_ = 256;
constexpr int R_ = 8;
constexpr int C1 = 48,  H1 = 64;   // conv1 out: 8 rot x 6
constexpr int C2 = 128, H2 = 32;   // conv2 out: 8 rot x 16
constexpr int C3 = 80,  H3 = 16;   // conv3 out: 8 rot x 10

// ---------------- scratch (device globals; allocation-free rule) ----------------
__device__ float g_sw1[48 * 1 * 5];
__device__ float g_sw2[128 * 48 * 5];
__device__ float g_sw3[80 * 128 * 5];
__device__ float g_y1[(size_t)B_ * C1 * H1 * H1];  // 201 MB
__device__ float g_p1[(size_t)B_ * C1 * H2 * H2];  // 50 MB
__device__ float g_y2[(size_t)B_ * C2 * H2 * H2];  // 134 MB
__device__ float g_p2[(size_t)B_ * C2 * H3 * H3];  // 33.5 MB
__device__ float g_y3[(size_t)B_ * C3 * H3 * H3];  // 21 MB
__device__ float g_psum[B_ * C2];
__device__ float g_psq[B_ * C2];
__device__ float g_scale[C2];
__device__ float g_shift[C2];

// pad tables: top and left pads per rotation row (from reference L)
__device__ const int c_LT[8][3] = {{2,1,0},{2,1,1},{2,1,0},{1,1,1},{0,1,2},{0,1,2},{0,1,2},{1,1,1}};
__device__ const int c_LL[8][3] = {{0,1,2},{1,1,1},{2,1,0},{2,1,0},{2,1,0},{1,1,1},{0,1,2},{0,1,2}};

// Sparse tap offsets per rotation class (cls = r & 3).
// cls0: anti-diagonal  (oy,ox)=(2-s, s-2)
// cls1: vertical       (oy,ox)=(1-s, 0) for s<4, slot 4 is a zero-weight dummy
// cls2: main diagonal  (oy,ox)=(2-s, 2-s)
// cls3: horizontal     (oy,ox)=(0,   2-s)
__device__ __forceinline__ void taps(int cls, int oy[5], int ox[5]) {
#pragma unroll
    for (int s = 0; s < 5; s++) {
        int a = 2 - s;
        if (cls == 0)      { oy[s] = a;                    ox[s] = -a; }
        else if (cls == 1) { oy[s] = (s < 4) ? (1 - s) : 0; ox[s] = 0;  }
        else if (cls == 2) { oy[s] = a;                    ox[s] = a;  }
        else               { oy[s] = 0;                    ox[s] = a;  }
    }
}

// ---------------- build sparse effective kernels ----------------
__global__ void k_build(const float* __restrict__ w1, const float* __restrict__ w2,
                        const float* __restrict__ w3)
{
    int idx = blockIdx.x * blockDim.x + threadIdx.x;
    const float* w; float* out;
    int oc, ic, icfull, ocper, g;
    if (idx < 48)                  { w = w1; out = g_sw1; oc = idx; ic = 0; icfull = 1;   ocper = 6;  g = 0;  }
    else if (idx < 48 + 6144)      { int p = idx - 48;        w = w2; out = g_sw2; oc = p / 48;  ic = p % 48;  icfull = 48;  ocper = 16; g = 6;  }
    else if (idx < 48 + 6144 + 10240) { int p = idx - 48 - 6144; w = w3; out = g_sw3; oc = p / 128; ic = p % 128; icfull = 128; ocper = 10; g = 16; }
    else return;

    int i  = oc / ocper;
    int co = oc % ocper;
    int i2 = (i + 4) & 7;
    int cls = i & 3;
    int sic = ic;
    if (g) {                     // rotateChannel applied i times: roll channel groups by +i
        int rin = ic / g, gg = ic - rin * g;
        sic = ((rin - i) & 7) * g + gg;
    }
    float acc[5] = {0.f, 0.f, 0.f, 0.f, 0.f};
#pragma unroll
    for (int j = 0; j < 3; j++) {
#pragma unroll
        for (int k = 0; k < 3; k++) {
            int dy = c_LT[i][j] + c_LT[i2][k];
            int dx = c_LL[i][j] + c_LL[i2][k];
            int slot = (cls == 1) ? (dy - 1) : ((cls == 3) ? dx : dy);
            float v = w[(co * icfull + sic) * 9 + j * 3 + k];
#pragma unroll
            for (int s = 0; s < 5; s++) if (slot == s) acc[s] += v;
        }
    }
#pragma unroll
    for (int s = 0; s < 5; s++) out[(oc * icfull + ic) * 5 + s] = acc[s];
}

// ---------------- conv1: [B,1,64,64] -> y1 [B,48,64,64] ----------------
__global__ __launch_bounds__(256) void k_conv1(const float* __restrict__ x)
{
    int b  = blockIdx.x >> 2;
    int ty = blockIdx.x & 3;
    int r  = blockIdx.y;
    int cls = r & 3;
    __shared__ float s_in[20][68];
    __shared__ float s_w[30];
    int t = threadIdx.x;
    if (t < 30) s_w[t] = g_sw1[r * 30 + t];
    const float* xb = x + (size_t)b * 4096;
    int y0 = ty * 16;
    for (int i = t; i < 20 * 68; i += 256) {
        int yy = i / 68, xx = i - yy * 68;
        int gy = y0 + yy - 2, gx = xx - 2;
        float v = 0.f;
        if ((unsigned)gy < 64u && (unsigned)gx < 64u) v = xb[gy * 64 + gx];
        s_in[yy][xx] = v;
    }
    __syncthreads();
    int oy[5], ox[5]; taps(cls, oy, ox);
    int row = t >> 4;
    int x0  = (t & 15) << 2;
    float inv[5][4];
#pragma unroll
    for (int s = 0; s < 5; s++)
#pragma unroll
        for (int i = 0; i < 4; i++)
            inv[s][i] = s_in[row + 2 + oy[s]][x0 + 2 + ox[s] + i];
#pragma unroll
    for (int oc = 0; oc < 6; oc++) {
        float a0 = 0.f, a1 = 0.f, a2 = 0.f, a3 = 0.f;
#pragma unroll
        for (int s = 0; s < 5; s++) {
            float wv = s_w[oc * 5 + s];
            a0 = fmaf(wv, inv[s][0], a0);
            a1 = fmaf(wv, inv[s][1], a1);
            a2 = fmaf(wv, inv[s][2], a2);
            a3 = fmaf(wv, inv[s][3], a3);
        }
        float4 o = make_float4(a0, a1, a2, a3);
        *(float4*)&g_y1[(((size_t)b * 48 + r * 6 + oc) * 64 + (y0 + row)) * 64 + x0] = o;
    }
}

// ---------------- BN stats: per-plane partial sums (deterministic 2-stage) ----------------
__global__ void k_stats_partial(const float* __restrict__ src, int hw4,
                                float* __restrict__ psum, float* __restrict__ psq)
{
    int plane = blockIdx.x;
    const float4* p = (const float4*)(src + (size_t)plane * hw4 * 4);
    float s = 0.f, q = 0.f;
    for (int i = threadIdx.x; i < hw4; i += blockDim.x) {
        float4 v = p[i];
        s += v.x + v.y + v.z + v.w;
        q += v.x * v.x + v.y * v.y + v.z * v.z + v.w * v.w;
    }
    __shared__ float ss[256], sq[256];
    int t = threadIdx.x;
    ss[t] = s; sq[t] = q; __syncthreads();
    for (int st = 128; st > 0; st >>= 1) {
        if (t < st) { ss[t] += ss[t + st]; sq[t] += sq[t + st]; }
        __syncthreads();
    }
    if (t == 0) { psum[plane] = ss[0]; psq[plane] = sq[0]; }
}

__global__ void k_stats_final(const float* __restrict__ psum, const float* __restrict__ psq,
                              const float* __restrict__ gamma, const float* __restrict__ beta,
                              int Cc, int CH, float invN)
{
    int c = threadIdx.x;
    if (c >= Cc) return;
    float S = 0.f, Q = 0.f;
    for (int b = 0; b < B_; b++) {
        int base = b * CH + c;
        for (int rr = 0; rr < R_; rr++) { S += psum[base + rr * Cc]; Q += psq[base + rr * Cc]; }
    }
    float mean = S * invN;
    float var  = Q * invN - mean * mean;
    float sc = gamma[c] / sqrtf(var + 1e-5f);
    float sh = beta[c] - mean * sc;
    for (int rr = 0; rr < R_; rr++) { g_scale[rr * Cc + c] = sc; g_shift[rr * Cc + c] = sh; }
}

// ---------------- fused BN + ReLU + 2x2 maxpool ----------------
__global__ void k_bnpool(const float* __restrict__ src, float* __restrict__ dst,
                         int Hout, int CH)
{
    int plane = blockIdx.x;        // b*CH + ch
    int ch = plane % CH;
    float sc = g_scale[ch], sh = g_shift[ch];
    int t = threadIdx.x;           // Hout * (Hout/4) threads
    int nq = Hout >> 2;
    int q = t % nq, yo = t / nq;
    int Hin = Hout * 2;
    const float* p = src + ((size_t)plane * Hin + 2 * yo) * Hin + q * 8;
    float4 r0a = *(const float4*)p;
    float4 r0b = *(const float4*)(p + 4);
    float4 r1a = *(const float4*)(p + Hin);
    float4 r1b = *(const float4*)(p + Hin + 4);
    float v[16] = {r0a.x, r0a.y, r0a.z, r0a.w, r0b.x, r0b.y, r0b.z, r0b.w,
                   r1a.x, r1a.y, r1a.z, r1a.w, r1b.x, r1b.y, r1b.z, r1b.w};
    float4 o;
    float* ov = &o.x;
#pragma unroll
    for (int i = 0; i < 4; i++) {
        float m0 = fmaxf(0.f, fmaf(sc, v[2 * i],     sh));
        float m1 = fmaxf(0.f, fmaf(sc, v[2 * i + 1], sh));
        float m2 = fmaxf(0.f, fmaf(sc, v[8 + 2 * i],     sh));
        float m3 = fmaxf(0.f, fmaf(sc, v[8 + 2 * i + 1], sh));
        ov[i] = fmaxf(fmaxf(m0, m1), fmaxf(m2, m3));
    }
    *(float4*)&dst[((size_t)plane * Hout + yo) * Hout + q * 4] = o;
}

// ---------------- conv2: p1 [B,48,32,32] -> y2 [B,128,32,32] ----------------
__global__ __launch_bounds__(256, 2) void k_conv2()
{
    int b = blockIdx.x;
    int r = blockIdx.y;
    int cls = r & 3;
    __shared__ float s_in[8][1296];     // 8 ic x 36x36 (halo)
    __shared__ float s_w[8][16][5];
    int t = threadIdx.x;
    int oy[5], ox[5]; taps(cls, oy, ox);
    int row = t >> 3;          // 0..31
    int x0  = (t & 7) << 2;    // 0..28
    float acc[16][4];
#pragma unroll
    for (int o = 0; o < 16; o++)
#pragma unroll
        for (int i = 0; i < 4; i++) acc[o][i] = 0.f;
    const float* pin = g_p1 + (size_t)b * 48 * 1024;
    const float* pw  = g_sw2 + (size_t)r * 16 * 48 * 5;
    for (int icc = 0; icc < 48; icc += 8) {
        for (int i = t; i < 8 * 1296; i += 256) {
            int ic = i / 1296; int rem = i - ic * 1296;
            int yy = rem / 36, xx = rem - yy * 36;
            int gy = yy - 2, gx = xx - 2;
            float v = 0.f;
            if ((unsigned)gy < 32u && (unsigned)gx < 32u) v = pin[(icc + ic) * 1024 + gy * 32 + gx];
            s_in[ic][rem] = v;
        }
        for (int i = t; i < 640; i += 256) {
            int ic = i / 80; int rem = i - ic * 80; int oc = rem / 5; int s = rem - oc * 5;
            s_w[ic][oc][s] = pw[(oc * 48 + icc + ic) * 5 + s];
        }
        __syncthreads();
#pragma unroll 1
        for (int ic = 0; ic < 8; ic++) {
            float inv[5][4];
#pragma unroll
            for (int s = 0; s < 5; s++) {
                int off = (row + 2 + oy[s]) * 36 + (x0 + 2 + ox[s]);
#pragma unroll
                for (int i = 0; i < 4; i++) inv[s][i] = s_in[ic][off + i];
            }
#pragma unroll
            for (int oc = 0; oc < 16; oc++) {
#pragma unroll
                for (int s = 0; s < 5; s++) {
                    float wv = s_w[ic][oc][s];
#pragma unroll
                    for (int i = 0; i < 4; i++) acc[oc][i] = fmaf(wv, inv[s][i], acc[oc][i]);
                }
            }
        }
        __syncthreads();
    }
    size_t base = (((size_t)b * 128) + r * 16) * 1024 + row * 32 + x0;
#pragma unroll
    for (int oc = 0; oc < 16; oc++) {
        float4 o = make_float4(acc[oc][0], acc[oc][1], acc[oc][2], acc[oc][3]);
        *(float4*)&g_y2[base + (size_t)oc * 1024] = o;
    }
}

// ---------------- conv3: p2 [B,128,16,16] -> y3 [B,80,16,16] ----------------
__global__ __launch_bounds__(256, 2) void k_conv3()
{
    int bb = blockIdx.x;      // 64 groups of 4 batches
    int r  = blockIdx.y;
    int cls = r & 3;
    __shared__ float s_in[4][4][400];  // [ic][batch][20x20]
    __shared__ float s_w[4][10][5];
    int t = threadIdx.x;
    int oy[5], ox[5]; taps(cls, oy, ox);
    int y = t >> 4, x = t & 15;
    float acc[4][10];
#pragma unroll
    for (int b_ = 0; b_ < 4; b_++)
#pragma unroll
        for (int oc = 0; oc < 10; oc++) acc[b_][oc] = 0.f;
    const float* pw = g_sw3 + (size_t)r * 10 * 128 * 5;
    for (int icc = 0; icc < 128; icc += 4) {
        for (int i = t; i < 6400; i += 256) {
            int ic = i / 1600; int rem = i - ic * 1600;
            int b_ = rem / 400; int rem2 = rem - b_ * 400;
            int yy = rem2 / 20, xx = rem2 - yy * 20;
            int gy = yy - 2, gx = xx - 2;
            float v = 0.f;
            if ((unsigned)gy < 16u && (unsigned)gx < 16u)
                v = g_p2[(((size_t)(bb * 4 + b_) * 128) + icc + ic) * 256 + gy * 16 + gx];
            s_in[ic][b_][rem2] = v;
        }
        for (int i = t; i < 200; i += 256) {
            int ic = i / 50; int rem = i - ic * 50; int oc = rem / 5; int s = rem - oc * 5;
            s_w[ic][oc][s] = pw[(oc * 128 + icc + ic) * 5 + s];
        }
        __syncthreads();
#pragma unroll 1
        for (int ic = 0; ic < 4; ic++) {
            float inv[5][4];
#pragma unroll
            for (int s = 0; s < 5; s++) {
                int off = (y + 2 + oy[s]) * 20 + (x + 2 + ox[s]);
#pragma unroll
                for (int b_ = 0; b_ < 4; b_++) inv[s][b_] = s_in[ic][b_][off];
            }
#pragma unroll
            for (int oc = 0; oc < 10; oc++) {
#pragma unroll
                for (int s = 0; s < 5; s++) {
                    float wv = s_w[ic][oc][s];
#pragma unroll
                    for (int b_ = 0; b_ < 4; b_++) acc[b_][oc] = fmaf(wv, inv[s][b_], acc[b_][oc]);
                }
            }
        }
        __syncthreads();
    }
#pragma unroll
    for (int b_ = 0; b_ < 4; b_++)
#pragma unroll
        for (int oc = 0; oc < 10; oc++)
            g_y3[(((size_t)(bb * 4 + b_) * 80) + r * 10 + oc) * 256 + y * 16 + x] = acc[b_][oc];
}

// ---------------- rotateMax (groups of 8 consecutive channels) + global max ----------------
__global__ void k_finalmax(float* __restrict__ out)
{
    int b = blockIdx.x;
    int t = threadIdx.x;     // 256 = one spatial position each
    __shared__ float sm[256];
    const float* p = g_y3 + (size_t)b * 80 * 256;
    for (int gp = 0; gp < 10; gp++) {
        float m = -3.4e38f;
#pragma unroll
        for (int ch = 0; ch < 8; ch++) m = fmaxf(m, p[(gp * 8 + ch) * 256 + t]);
        sm[t] = m; __syncthreads();
        for (int st = 128; st > 0; st >>= 1) {
            if (t < st) sm[t] = fmaxf(sm[t], sm[t + st]);
            __syncthreads();
        }
        if (t == 0) out[b * 10 + gp] = sm[0];
        __syncthreads();
    }
}

// ---------------- launch ----------------
extern "C" void kernel_launch(void* const* d_in, const int* in_sizes, int n_in,
                              void* d_out, int out_size)
{
    const float* x  = (const float*)d_in[0];
    const float* w1 = (const float*)d_in[1];
    const float* g1 = (const float*)d_in[2];
    const float* b1 = (const float*)d_in[3];
    const float* w2 = (const float*)d_in[4];
    const float* g2 = (const float*)d_in[5];
    const float* b2 = (const float*)d_in[6];
    const float* w3 = (const float*)d_in[7];
    float* out = (float*)d_out;

    float *py1, *py2, *pp1, *pp2, *ppsum, *ppsq;
    cudaGetSymbolAddress((void**)&py1, g_y1);
    cudaGetSymbolAddress((void**)&py2, g_y2);
    cudaGetSymbolAddress((void**)&pp1, g_p1);
    cudaGetSymbolAddress((void**)&pp2, g_p2);
    cudaGetSymbolAddress((void**)&ppsum, g_psum);
    cudaGetSymbolAddress((void**)&ppsq, g_psq);

    k_build<<<65, 256>>>(w1, w2, w3);
    k_conv1<<<dim3(1024, 8), 256>>>(x);

    k_stats_partial<<<256 * 48, 256>>>(py1, 1024, ppsum, ppsq);            // hw4 = 4096/4
    k_stats_final<<<1, 32>>>(ppsum, ppsq, g1, b1, 6, 48, 1.f / 8388608.f); // N = 256*8*64*64
    k_bnpool<<<256 * 48, 256>>>(py1, pp1, 32, 48);

    k_conv2<<<dim3(256, 8), 256>>>();

    k_stats_partial<<<256 * 128, 256>>>(py2, 256, ppsum, ppsq);            // hw4 = 1024/4
    k_stats_final<<<1, 32>>>(ppsum, ppsq, g2, b2, 16, 128, 1.f / 2097152.f); // N = 256*8*32*32
    k_bnpool<<<256 * 128, 64>>>(py2, pp2, 16, 128);

    k_conv3<<<dim3(64, 8), 256>>>();
    k_finalmax<<<256, 256>>>(out);
}

// round 3
// speedup vs baseline: 1.2387x; 1.2387x over previous
#include <cuda_runtime.h>

// ---------------- sizes ----------------
constexpr int B_ = 256;
constexpr int R_ = 8;
constexpr int C2 = 128;

// ---------------- scratch (device globals; allocation-free rule) ----------------
__device__ float g_sw1[48 * 1 * 5];
__device__ float g_sw2[128 * 48 * 5];
__device__ float g_sw3[80 * 128 * 5];
__device__ float g_p1[(size_t)B_ * 48 * 32 * 32];    // 50 MB
__device__ float g_y2[(size_t)B_ * 128 * 32 * 32];   // 134 MB
__device__ float g_p2[(size_t)B_ * 128 * 16 * 16];   // 33.5 MB
__device__ float g_y3[(size_t)B_ * 80 * 16 * 16];    // 21 MB
__device__ float g_psum[B_ * R_ * 16];
__device__ float g_psq[B_ * R_ * 16];
__device__ float g_scale[C2];
__device__ float g_shift[C2];

// pad tables: top and left pads per rotation row (from reference L)
__device__ const int c_LT[8][3] = {{2,1,0},{2,1,1},{2,1,0},{1,1,1},{0,1,2},{0,1,2},{0,1,2},{1,1,1}};
__device__ const int c_LL[8][3] = {{0,1,2},{1,1,1},{2,1,0},{2,1,0},{2,1,0},{1,1,1},{0,1,2},{0,1,2}};

// Sparse tap offsets per rotation class (cls = r & 3).
__device__ __forceinline__ void taps(int cls, int oy[5], int ox[5]) {
#pragma unroll
    for (int s = 0; s < 5; s++) {
        int a = 2 - s;
        if (cls == 0)      { oy[s] = a;                     ox[s] = -a; }
        else if (cls == 1) { oy[s] = (s < 4) ? (1 - s) : 0; ox[s] = 0;  }
        else if (cls == 2) { oy[s] = a;                     ox[s] = a;  }
        else               { oy[s] = 0;                     ox[s] = a;  }
    }
}

// ---------------- build sparse effective kernels ----------------
__global__ void k_build(const float* __restrict__ w1, const float* __restrict__ w2,
                        const float* __restrict__ w3)
{
    int idx = blockIdx.x * blockDim.x + threadIdx.x;
    const float* w; float* out;
    int oc, ic, icfull, ocper, g;
    if (idx < 48)                     { w = w1; out = g_sw1; oc = idx; ic = 0; icfull = 1;   ocper = 6;  g = 0;  }
    else if (idx < 48 + 6144)         { int p = idx - 48;        w = w2; out = g_sw2; oc = p / 48;  ic = p % 48;  icfull = 48;  ocper = 16; g = 6;  }
    else if (idx < 48 + 6144 + 10240) { int p = idx - 48 - 6144; w = w3; out = g_sw3; oc = p / 128; ic = p % 128; icfull = 128; ocper = 10; g = 16; }
    else return;

    int i  = oc / ocper;
    int co = oc % ocper;
    int i2 = (i + 4) & 7;
    int cls = i & 3;
    int sic = ic;
    if (g) {                     // rotateChannel applied i times
        int rin = ic / g, gg = ic - rin * g;
        sic = ((rin - i) & 7) * g + gg;
    }
    float acc[5] = {0.f, 0.f, 0.f, 0.f, 0.f};
#pragma unroll
    for (int j = 0; j < 3; j++) {
#pragma unroll
        for (int k = 0; k < 3; k++) {
            int dy = c_LT[i][j] + c_LT[i2][k];
            int dx = c_LL[i][j] + c_LL[i2][k];
            int slot = (cls == 1) ? (dy - 1) : ((cls == 3) ? dx : dy);
            float v = w[(co * icfull + sic) * 9 + j * 3 + k];
#pragma unroll
            for (int s = 0; s < 5; s++) if (slot == s) acc[s] += v;
        }
    }
#pragma unroll
    for (int s = 0; s < 5; s++) out[(oc * icfull + ic) * 5 + s] = acc[s];
}

// ---------------- conv1 pass A: conv + exact per-plane stats (no y1 materialization) ----------------
__global__ __launch_bounds__(256) void k_conv1_stats(const float* __restrict__ x)
{
    int b = blockIdx.x, r = blockIdx.y, cls = r & 3;
    __shared__ float s_in[68 * 68];
    int t = threadIdx.x;
    const float* xb = x + (size_t)b * 4096;
    for (int i = t; i < 68 * 68; i += 256) {
        int yy = i / 68, xx = i - yy * 68;
        int gy = yy - 2, gx = xx - 2;
        float v = 0.f;
        if ((unsigned)gy < 64u && (unsigned)gx < 64u) v = xb[gy * 64 + gx];
        s_in[i] = v;
    }
    float w[6][5];
#pragma unroll
    for (int oc = 0; oc < 6; oc++)
#pragma unroll
        for (int s = 0; s < 5; s++) w[oc][s] = g_sw1[(r * 6 + oc) * 5 + s];
    __syncthreads();

    int oy[5], ox[5]; taps(cls, oy, ox);
    int r0 = t >> 4, x0 = (t & 15) << 2;
    float ssum[6] = {0,0,0,0,0,0}, ssq[6] = {0,0,0,0,0,0};
#pragma unroll
    for (int rr = 0; rr < 4; rr++) {
        int row = r0 + rr * 16;
        float inv[5][4];
#pragma unroll
        for (int s = 0; s < 5; s++) {
            int off = (row + 2 + oy[s]) * 68 + x0 + 2 + ox[s];
#pragma unroll
            for (int i = 0; i < 4; i++) inv[s][i] = s_in[off + i];
        }
#pragma unroll
        for (int oc = 0; oc < 6; oc++) {
            float a0 = 0.f, a1 = 0.f, a2 = 0.f, a3 = 0.f;
#pragma unroll
            for (int s = 0; s < 5; s++) {
                float wv = w[oc][s];
                a0 = fmaf(wv, inv[s][0], a0);
                a1 = fmaf(wv, inv[s][1], a1);
                a2 = fmaf(wv, inv[s][2], a2);
                a3 = fmaf(wv, inv[s][3], a3);
            }
            ssum[oc] += a0 + a1 + a2 + a3;
            ssq[oc]  += a0 * a0 + a1 * a1 + a2 * a2 + a3 * a3;
        }
    }
    // block reduce (deterministic: shuffle tree + fixed-order smem sum)
    __shared__ float rs[6][8], rq[6][8];
    int lane = t & 31, wid = t >> 5;
#pragma unroll
    for (int oc = 0; oc < 6; oc++) {
        float s = ssum[oc], q = ssq[oc];
#pragma unroll
        for (int off = 16; off; off >>= 1) {
            s += __shfl_down_sync(0xffffffffu, s, off);
            q += __shfl_down_sync(0xffffffffu, q, off);
        }
        if (lane == 0) { rs[oc][wid] = s; rq[oc][wid] = q; }
    }
    __syncthreads();
    if (t < 6) {
        float S = 0.f, Q = 0.f;
#pragma unroll
        for (int wdx = 0; wdx < 8; wdx++) { S += rs[t][wdx]; Q += rq[t][wdx]; }
        int p = (b * 8 + r) * 6 + t;
        g_psum[p] = S; g_psq[p] = Q;
    }
}

// ---------------- parallel BN stats finalize: one block per channel ----------------
__global__ void k_stats_final(const float* __restrict__ gamma, const float* __restrict__ beta,
                              int Cc, float invN)
{
    int c = blockIdx.x;
    float S = 0.f, Q = 0.f;
    for (int i = threadIdx.x; i < 2048; i += 256) {
        S += g_psum[i * Cc + c];
        Q += g_psq[i * Cc + c];
    }
    __shared__ float ss[256], sq[256];
    int t = threadIdx.x;
    ss[t] = S; sq[t] = Q; __syncthreads();
    for (int st = 128; st > 0; st >>= 1) {
        if (t < st) { ss[t] += ss[t + st]; sq[t] += sq[t + st]; }
        __syncthreads();
    }
    if (t == 0) {
        float mean = ss[0] * invN;
        float var  = sq[0] * invN - mean * mean;
        float sc = gamma[c] / sqrtf(var + 1e-5f);
        float sh = beta[c] - mean * sc;
        for (int rr = 0; rr < R_; rr++) { g_scale[rr * Cc + c] = sc; g_shift[rr * Cc + c] = sh; }
    }
}

// ---------------- conv1 pass B: recompute conv + BN + ReLU + pool -> p1 ----------------
__global__ __launch_bounds__(256) void k_conv1_pool(const float* __restrict__ x)
{
    int b = blockIdx.x, r = blockIdx.y, cls = r & 3;
    __shared__ float s_in[68 * 68];
    int t = threadIdx.x;
    const float* xb = x + (size_t)b * 4096;
    for (int i = t; i < 68 * 68; i += 256) {
        int yy = i / 68, xx = i - yy * 68;
        int gy = yy - 2, gx = xx - 2;
        float v = 0.f;
        if ((unsigned)gy < 64u && (unsigned)gx < 64u) v = xb[gy * 64 + gx];
        s_in[i] = v;
    }
    float w[6][5];
#pragma unroll
    for (int oc = 0; oc < 6; oc++)
#pragma unroll
        for (int s = 0; s < 5; s++) w[oc][s] = g_sw1[(r * 6 + oc) * 5 + s];
    __syncthreads();

    int oy[5], ox[5]; taps(cls, oy, ox);
    int py = t >> 3, px0 = (t & 7) << 2;   // pooled: 32 rows x 32 cols, 4 cols/thread
    float mx[6][4];
#pragma unroll
    for (int oc = 0; oc < 6; oc++)
#pragma unroll
        for (int i = 0; i < 4; i++) mx[oc][i] = -3.4e38f;

#pragma unroll
    for (int i = 0; i < 4; i++) {
#pragma unroll
        for (int dy = 0; dy < 2; dy++) {
#pragma unroll
            for (int dx = 0; dx < 2; dx++) {
                int cy = 2 * py + dy, cx = 2 * (px0 + i) + dx;
                float in5[5];
#pragma unroll
                for (int s = 0; s < 5; s++) in5[s] = s_in[(cy + 2 + oy[s]) * 68 + cx + 2 + ox[s]];
#pragma unroll
                for (int oc = 0; oc < 6; oc++) {
                    float a = 0.f;
#pragma unroll
                    for (int s = 0; s < 5; s++) a = fmaf(w[oc][s], in5[s], a);
                    mx[oc][i] = fmaxf(mx[oc][i], a);
                }
            }
        }
    }
#pragma unroll
    for (int oc = 0; oc < 6; oc++) {
        float sc = g_scale[r * 6 + oc], sh = g_shift[r * 6 + oc];
        float4 o;
        o.x = fmaxf(0.f, fmaf(sc, mx[oc][0], sh));
        o.y = fmaxf(0.f, fmaf(sc, mx[oc][1], sh));
        o.z = fmaxf(0.f, fmaf(sc, mx[oc][2], sh));
        o.w = fmaxf(0.f, fmaf(sc, mx[oc][3], sh));
        *(float4*)&g_p1[((size_t)(b * 48 + r * 6 + oc)) * 1024 + py * 32 + px0] = o;
    }
}

// ---------------- conv2: p1 [B,48,32,32] -> y2 [B,128,32,32] + fused stats ----------------
__global__ __launch_bounds__(256, 2) void k_conv2(int b_base)
{
    int b = b_base + blockIdx.x;
    int r = blockIdx.y;
    int cls = r & 3;
    __shared__ float s_in[8][1296];                   // 8 ic x 36x36 halo
    __shared__ __align__(16) float s_w[8][16][8];     // padded: float4 + scalar loads
    int t = threadIdx.x;
    int oy[5], ox[5]; taps(cls, oy, ox);
    int row = t >> 3;          // 0..31
    int x0  = (t & 7) << 2;    // 0..28
    float acc[16][4];
#pragma unroll
    for (int o = 0; o < 16; o++)
#pragma unroll
        for (int i = 0; i < 4; i++) acc[o][i] = 0.f;
    const float* pin = g_p1 + (size_t)b * 48 * 1024;
    const float* pw  = g_sw2 + (size_t)r * 16 * 48 * 5;
    for (int icc = 0; icc < 48; icc += 8) {
        for (int i = t; i < 8 * 1296; i += 256) {
            int ic = i / 1296; int rem = i - ic * 1296;
            int yy = rem / 36, xx = rem - yy * 36;
            int gy = yy - 2, gx = xx - 2;
            float v = 0.f;
            if ((unsigned)gy < 32u && (unsigned)gx < 32u) v = pin[(icc + ic) * 1024 + gy * 32 + gx];
            s_in[ic][rem] = v;
        }
        for (int i = t; i < 640; i += 256) {
            int ic = i / 80; int rem = i - ic * 80; int oc = rem / 5; int s = rem - oc * 5;
            s_w[ic][oc][s] = pw[(oc * 48 + icc + ic) * 5 + s];
        }
        __syncthreads();
#pragma unroll 1
        for (int ic = 0; ic < 8; ic++) {
            float inv[5][4];
#pragma unroll
            for (int s = 0; s < 5; s++) {
                int off = (row + 2 + oy[s]) * 36 + (x0 + 2 + ox[s]);
#pragma unroll
                for (int i = 0; i < 4; i++) inv[s][i] = s_in[ic][off + i];
            }
#pragma unroll
            for (int oc = 0; oc < 16; oc++) {
                float4 w03 = *(const float4*)&s_w[ic][oc][0];
                float  w4  = s_w[ic][oc][4];
#pragma unroll
                for (int i = 0; i < 4; i++) {
                    float a = acc[oc][i];
                    a = fmaf(w03.x, inv[0][i], a);
                    a = fmaf(w03.y, inv[1][i], a);
                    a = fmaf(w03.z, inv[2][i], a);
                    a = fmaf(w03.w, inv[3][i], a);
                    a = fmaf(w4,   inv[4][i], a);
                    acc[oc][i] = a;
                }
            }
        }
        __syncthreads();
    }
    size_t base = (((size_t)b * 128) + r * 16) * 1024 + row * 32 + x0;
#pragma unroll
    for (int oc = 0; oc < 16; oc++) {
        float4 o = make_float4(acc[oc][0], acc[oc][1], acc[oc][2], acc[oc][3]);
        *(float4*)&g_y2[base + (size_t)oc * 1024] = o;
    }
    // fused exact per-plane stats (block == full plane per oc)
    __shared__ float rs[16][8], rq[16][8];
    int lane = t & 31, wid = t >> 5;
#pragma unroll
    for (int oc = 0; oc < 16; oc++) {
        float s = acc[oc][0] + acc[oc][1] + acc[oc][2] + acc[oc][3];
        float q = acc[oc][0] * acc[oc][0] + acc[oc][1] * acc[oc][1]
                + acc[oc][2] * acc[oc][2] + acc[oc][3] * acc[oc][3];
#pragma unroll
        for (int off = 16; off; off >>= 1) {
            s += __shfl_down_sync(0xffffffffu, s, off);
            q += __shfl_down_sync(0xffffffffu, q, off);
        }
        if (lane == 0) { rs[oc][wid] = s; rq[oc][wid] = q; }
    }
    __syncthreads();
    if (t < 16) {
        float S = 0.f, Q = 0.f;
#pragma unroll
        for (int wdx = 0; wdx < 8; wdx++) { S += rs[t][wdx]; Q += rq[t][wdx]; }
        int p = (b * 8 + r) * 16 + t;
        g_psum[p] = S; g_psq[p] = Q;
    }
}

// ---------------- fused BN + ReLU + 2x2 maxpool: y2 -> p2 ----------------
__global__ void k_bnpool2()
{
    int plane = blockIdx.x;        // b*128 + ch
    int ch = plane & 127;
    float sc = g_scale[ch], sh = g_shift[ch];
    int t = threadIdx.x;           // 64 threads: 16 rows x 4 quads
    int q = t & 3, yo = t >> 2;
    const float* p = g_y2 + ((size_t)plane * 32 + 2 * yo) * 32 + q * 8;
    float4 r0a = *(const float4*)p;
    float4 r0b = *(const float4*)(p + 4);
    float4 r1a = *(const float4*)(p + 32);
    float4 r1b = *(const float4*)(p + 36);
    float v[16] = {r0a.x, r0a.y, r0a.z, r0a.w, r0b.x, r0b.y, r0b.z, r0b.w,
                   r1a.x, r1a.y, r1a.z, r1a.w, r1b.x, r1b.y, r1b.z, r1b.w};
    float4 o; float* ov = &o.x;
#pragma unroll
    for (int i = 0; i < 4; i++) {
        float m0 = fmaxf(0.f, fmaf(sc, v[2 * i],     sh));
        float m1 = fmaxf(0.f, fmaf(sc, v[2 * i + 1], sh));
        float m2 = fmaxf(0.f, fmaf(sc, v[8 + 2 * i],     sh));
        float m3 = fmaxf(0.f, fmaf(sc, v[8 + 2 * i + 1], sh));
        ov[i] = fmaxf(fmaxf(m0, m1), fmaxf(m2, m3));
    }
    *(float4*)&g_p2[((size_t)plane * 16 + yo) * 16 + q * 4] = o;
}

// ---------------- conv3: p2 [B,128,16,16] -> y3 [B,80,16,16] ----------------
__global__ __launch_bounds__(256, 2) void k_conv3()
{
    int bb = blockIdx.x;      // 64 groups of 4 batches
    int r  = blockIdx.y;
    int cls = r & 3;
    __shared__ float s_in[4][4][400];                 // [ic][batch][20x20]
    __shared__ __align__(16) float s_w[4][10][8];
    int t = threadIdx.x;
    int oy[5], ox[5]; taps(cls, oy, ox);
    int y = t >> 4, x = t & 15;
    float acc[4][10];
#pragma unroll
    for (int b_ = 0; b_ < 4; b_++)
#pragma unroll
        for (int oc = 0; oc < 10; oc++) acc[b_][oc] = 0.f;
    const float* pw = g_sw3 + (size_t)r * 10 * 128 * 5;
    for (int icc = 0; icc < 128; icc += 4) {
        for (int i = t; i < 6400; i += 256) {
            int ic = i / 1600; int rem = i - ic * 1600;
            int b_ = rem / 400; int rem2 = rem - b_ * 400;
            int yy = rem2 / 20, xx = rem2 - yy * 20;
            int gy = yy - 2, gx = xx - 2;
            float v = 0.f;
            if ((unsigned)gy < 16u && (unsigned)gx < 16u)
                v = g_p2[(((size_t)(bb * 4 + b_) * 128) + icc + ic) * 256 + gy * 16 + gx];
            s_in[ic][b_][rem2] = v;
        }
        for (int i = t; i < 200; i += 256) {
            int ic = i / 50; int rem = i - ic * 50; int oc = rem / 5; int s = rem - oc * 5;
            s_w[ic][oc][s] = pw[(oc * 128 + icc + ic) * 5 + s];
        }
        __syncthreads();
#pragma unroll 1
        for (int ic = 0; ic < 4; ic++) {
            float inv[5][4];
#pragma unroll
            for (int s = 0; s < 5; s++) {
                int off = (y + 2 + oy[s]) * 20 + (x + 2 + ox[s]);
#pragma unroll
                for (int b_ = 0; b_ < 4; b_++) inv[s][b_] = s_in[ic][b_][off];
            }
#pragma unroll
            for (int oc = 0; oc < 10; oc++) {
                float4 w03 = *(const float4*)&s_w[ic][oc][0];
                float  w4  = s_w[ic][oc][4];
#pragma unroll
                for (int b_ = 0; b_ < 4; b_++) {
                    float a = acc[b_][oc];
                    a = fmaf(w03.x, inv[0][b_], a);
                    a = fmaf(w03.y, inv[1][b_], a);
                    a = fmaf(w03.z, inv[2][b_], a);
                    a = fmaf(w03.w, inv[3][b_], a);
                    a = fmaf(w4,   inv[4][b_], a);
                    acc[b_][oc] = a;
                }
            }
        }
        __syncthreads();
    }
#pragma unroll
    for (int b_ = 0; b_ < 4; b_++)
#pragma unroll
        for (int oc = 0; oc < 10; oc++)
            g_y3[(((size_t)(bb * 4 + b_) * 80) + r * 10 + oc) * 256 + y * 16 + x] = acc[b_][oc];
}

// ---------------- rotateMax (groups of 8 consecutive channels) + global max ----------------
__global__ void k_finalmax(float* __restrict__ out)
{
    int b = blockIdx.x;
    int t = threadIdx.x;
    __shared__ float sm[256];
    const float* p = g_y3 + (size_t)b * 80 * 256;
    for (int gp = 0; gp < 10; gp++) {
        float m = -3.4e38f;
#pragma unroll
        for (int ch = 0; ch < 8; ch++) m = fmaxf(m, p[(gp * 8 + ch) * 256 + t]);
        sm[t] = m; __syncthreads();
        for (int st = 128; st > 0; st >>= 1) {
            if (t < st) sm[t] = fmaxf(sm[t], sm[t + st]);
            __syncthreads();
        }
        if (t == 0) out[b * 10 + gp] = sm[0];
        __syncthreads();
    }
}

// ---------------- launch ----------------
extern "C" void kernel_launch(void* const* d_in, const int* in_sizes, int n_in,
                              void* d_out, int out_size)
{
    const float* x  = (const float*)d_in[0];
    const float* w1 = (const float*)d_in[1];
    const float* g1 = (const float*)d_in[2];
    const float* b1 = (const float*)d_in[3];
    const float* w2 = (const float*)d_in[4];
    const float* g2 = (const float*)d_in[5];
    const float* b2 = (const float*)d_in[6];
    const float* w3 = (const float*)d_in[7];
    float* out = (float*)d_out;

    k_build<<<65, 256>>>(w1, w2, w3);
    k_conv1_stats<<<dim3(256, 8), 256>>>(x);
    k_stats_final<<<6, 256>>>(g1, b1, 6, 1.f / 8388608.f);     // N = 256*8*64*64
    k_conv1_pool<<<dim3(256, 8), 256>>>(x);
    k_conv2<<<dim3(128, 8), 256>>>(0);
    k_conv2<<<dim3(128, 8), 256>>>(128);                        // launch #6 -> ncu capture
    k_stats_final<<<16, 256>>>(g2, b2, 16, 1.f / 2097152.f);    // N = 256*8*32*32
    k_bnpool2<<<256 * 128, 64>>>();
    k_conv3<<<dim3(64, 8), 256>>>();
    k_finalmax<<<256, 256>>>(out);
}